// round 8
// baseline (speedup 1.0000x reference)
#include <cuda_runtime.h>

#define PLANES 96
#define BINS   25
#define HH     512
#define WW     512
#define HWF    262144.0f
#define NBLK   1536
#define FULLM  0xFFFFFFFFu
#define W0 0.015625f
#define W1 0.09375f
#define W2 0.234375f
#define W3 0.3125f

__device__ unsigned int g_hist[2][PLANES][BINS];
__device__ unsigned int g_ticket;

// Lane owns 4 UNIQUE contiguous input cols [4l, 4l+3] of its 128-col strip:
// one aligned float4; warp row = 512B contiguous, 100% line utilization.
// Halo words lane-overloaded: lane 0 e0..e2 = cols -3..-1 (strip>0);
// lane 31 e0,e1 = cols 128,129 (strip<3).
struct Row {
    float4 q;
    float  e0, e1, e2;
};

__device__ __forceinline__ void load_row(Row& R, const float* __restrict__ base,
                                         int r, int lane, int strip) {
    if ((unsigned)r < (unsigned)HH) {          // warp-uniform branch (r uniform)
        const float* rowp = base + (size_t)r * WW;
        R.q = *(const float4*)rowp;
        R.e0 = R.e1 = R.e2 = 0.f;
        if (lane == 0 && strip > 0) {
            float4 lh = *(const float4*)(rowp - 4);
            R.e0 = lh.y; R.e1 = lh.z; R.e2 = lh.w;   // cols -3,-2,-1
        }
        if (lane == 31 && strip < 3) {
            float2 rh = *(const float2*)(rowp + 4);  // cols 128,129
            R.e0 = rh.x; R.e1 = rh.y;
        }
    } else {
        R.q = make_float4(0.f, 0.f, 0.f, 0.f);
        R.e0 = R.e1 = R.e2 = 0.f;
    }
}

// Horizontal 7-tap pascal, stride 2, 2 outputs/lane (cols 4l, 4l+2).
// Tap ordering identical to the rel_err-0.0 kernels.
__device__ __forceinline__ void hconv(const Row& R, int lane, float h[2]) {
    float m1 = __shfl_up_sync(FULLM, R.q.w, 1);     // col 4l-1
    float m2 = __shfl_up_sync(FULLM, R.q.z, 1);     // col 4l-2
    float m3 = __shfl_up_sync(FULLM, R.q.y, 1);     // col 4l-3
    float p4 = __shfl_down_sync(FULLM, R.q.x, 1);   // col 4l+4
    float p5 = __shfl_down_sync(FULLM, R.q.y, 1);   // col 4l+5
    if (lane == 0)  { m3 = R.e0; m2 = R.e1; m1 = R.e2; }
    if (lane == 31) { p4 = R.e0; p5 = R.e1; }

    h[0] = W0*(m3    + R.q.w) + W1*(m2    + R.q.z) + W2*(m1    + R.q.y) + W3*R.q.x;
    h[1] = W0*(m1    + p5)    + W1*(R.q.x + p4)    + W2*(R.q.y + R.q.w) + W3*R.q.z;
}

__global__ __launch_bounds__(128, 9) void fused_hist_loss_kernel(
    const float* __restrict__ x, const float* __restrict__ y,
    float* __restrict__ out)
{
    __shared__ unsigned int s_cnt[BINS][128];
    __shared__ float        s_red[128];
    __shared__ unsigned int s_last;

    const int tid  = threadIdx.x;
    const int lane = tid & 31;
    const int wrp  = tid >> 5;

    const int bi    = blockIdx.x;          // 1536 = 192 planes * 2 block-bands * 4 strips
    const int strip = bi & 3;
    const int bb    = (bi >> 2) & 1;
    const int pz    = bi >> 3;             // 0..191
    const int tsel  = (pz >= PLANES) ? 1 : 0;
    const int plane = pz - tsel * PLANES;

    const float* __restrict__ in = (tsel ? y : x) + (size_t)plane * HH * WW;
    const float* base = in + strip * 128 + 4 * lane;

    const int band = bb * 4 + wrp;         // 0..7, 32 output rows each
    const int rb0  = 64 * band - 3;        // input rows rb0..rb0+68
    unsigned int* myc = &s_cnt[0][tid];

    // 4-row ring buffer (R6-proven depth; Row is only 7 regs here).
    Row R0, R1, R2, R3;
    load_row(R0, base, rb0,     lane, strip);
    load_row(R1, base, rb0 + 1, lane, strip);
    load_row(R2, base, rb0 + 2, lane, strip);
    load_row(R3, base, rb0 + 3, lane, strip);

#pragma unroll
    for (int i = tid; i < BINS * 128; i += 128) ((unsigned int*)s_cnt)[i] = 0u;
    __syncthreads();

    float h[2], accA[2], accB[2], accC[2];

    // Prologue: consume rows 0..2, replenish slots with rows 4..6.
    hconv(R0, lane, h);
#pragma unroll
    for (int j = 0; j < 2; j++) { accA[j] = 0.f; accB[j] = W0 * h[j]; }
    load_row(R0, base, rb0 + 4, lane, strip);
    hconv(R1, lane, h);
#pragma unroll
    for (int j = 0; j < 2; j++) accB[j] = fmaf(W1, h[j], accB[j]);
    load_row(R1, base, rb0 + 5, lane, strip);
    hconv(R2, lane, h);
#pragma unroll
    for (int j = 0; j < 2; j++) { accB[j] = fmaf(W2, h[j], accB[j]); accC[j] = W0 * h[j]; }
    load_row(R2, base, rb0 + 6, lane, strip);

    // Pair g consumes rows (3+2g, 4+2g), loads rows (7+2g, 8+2g) into the
    // same slots. Odd rows alternate slots R3/R1, even rows R0/R2.
#define PAIR(RO, RE, g, DO_LOAD)                                              \
    do {                                                                       \
        hconv(RO, lane, h);                                                    \
        _Pragma("unroll")                                                      \
        for (int j = 0; j < 2; j++) {                                          \
            accA[j] = fmaf(W1, h[j], accA[j]);                                 \
            accB[j] = fmaf(W3, h[j], accB[j]);                                 \
            accC[j] = fmaf(W1, h[j], accC[j]);                                 \
        }                                                                      \
        if (DO_LOAD) load_row(RO, base, rb0 + 7 + 2 * (g), lane, strip);       \
        hconv(RE, lane, h);                                                    \
        _Pragma("unroll")                                                      \
        for (int j = 0; j < 2; j++) accA[j] = fmaf(W0, h[j], accA[j]);         \
        if ((g) > 0) {                                                         \
            _Pragma("unroll")                                                  \
            for (int j = 0; j < 2; j++) {                                      \
                float v = accA[j];                                             \
                if (v >= 0.0f && v <= 1.0f) {   /* torch.histc(v,25,0,1) */    \
                    int b = (int)(v * 25.0f); b = b > 24 ? 24 : b;             \
                    myc[b * 128] += 1u;                                        \
                }                                                              \
            }                                                                  \
        }                                                                      \
        _Pragma("unroll")                                                      \
        for (int j = 0; j < 2; j++) {                                          \
            accA[j] = fmaf(W2, h[j], accB[j]);                                 \
            accB[j] = fmaf(W2, h[j], accC[j]);                                 \
            accC[j] = W0 * h[j];                                               \
        }                                                                      \
        if (DO_LOAD) load_row(RE, base, rb0 + 8 + 2 * (g), lane, strip);       \
    } while (0)

#pragma unroll 1
    for (int gg = 0; gg < 15; gg++) {      // g = 0..29
        int g = 2 * gg;
        PAIR(R3, R0, g, 1);
        PAIR(R1, R2, g + 1, 1);
    }
    PAIR(R3, R0, 30, 1);                   // loads rows 67,68 (last valid)
    PAIR(R1, R2, 31, 0);
    PAIR(R3, R0, 32, 0);                   // retires output row 31
#undef PAIR

    __syncthreads();

    // Block-reduce private counters -> 25 global atomics.
    for (int bin = wrp; bin < BINS; bin += 4) {
        unsigned int sum = 0;
#pragma unroll
        for (int j = 0; j < 4; j++) sum += s_cnt[bin][lane + 32 * j];
#pragma unroll
        for (int off = 16; off; off >>= 1) sum += __shfl_down_sync(FULLM, sum, off);
        if (lane == 0) atomicAdd(&g_hist[tsel][plane][bin], sum);
    }

    // Last-block finalize.
    __threadfence();
    __syncthreads();
    if (tid == 0) {
        unsigned int t = atomicAdd(&g_ticket, 1u);
        s_last = (t == NBLK - 1) ? 1u : 0u;
    }
    __syncthreads();
    if (!s_last) return;

    float cosv = 0.0f;
    if (tid < PLANES) {
        float dot = 0.0f, nx = 0.0f, ny = 0.0f;
#pragma unroll
        for (int b = 0; b < BINS; b++) {
            float xv = (float)__ldcg(&g_hist[0][tid][b]);
            float yv = (float)__ldcg(&g_hist[1][tid][b]);
            dot = fmaf(xv, yv, dot);
            nx  = fmaf(xv, xv, nx);
            ny  = fmaf(yv, yv, ny);
        }
        float nxs = fmaxf(sqrtf(nx) * (1.0f / HWF), 1e-6f);
        float nys = fmaxf(sqrtf(ny) * (1.0f / HWF), 1e-6f);
        cosv = (dot * (1.0f / (HWF * HWF))) / (nxs * nys);
    }
    s_red[tid] = cosv;
    __syncthreads();
#pragma unroll
    for (int stride = 64; stride > 0; stride >>= 1) {
        if (tid < stride) s_red[tid] += s_red[tid + stride];
        __syncthreads();
    }
    if (tid == 0) out[0] = s_red[0] * (1.0f / 96.0f);

    __syncthreads();
    for (int i = tid; i < 2 * PLANES * BINS; i += 128)
        ((unsigned int*)g_hist)[i] = 0u;
    if (tid == 0) g_ticket = 0u;
}

extern "C" void kernel_launch(void* const* d_in, const int* in_sizes, int n_in,
                              void* d_out, int out_size) {
    const float* x = (const float*)d_in[0];
    const float* y = (const float*)d_in[1];
    fused_hist_loss_kernel<<<NBLK, 128>>>(x, y, (float*)d_out);
}